// round 3
// baseline (speedup 1.0000x reference)
#include <cuda_runtime.h>

#define DIM 8
typedef unsigned int u32;

// ---------------- bit-exact slow path (identical math to the passing R1 kernel) ----------------
__device__ __forceinline__ void closest_D8_exact(const float x[DIM], float out[DIM]) {
    float f[DIM], d[DIM];
    int isum = 0;
#pragma unroll
    for (int i = 0; i < DIM; ++i) {
        f[i] = rintf(x[i]);
        d[i] = x[i] - f[i];
        isum += __float2int_rn(f[i]);
    }
    int worst = 0;
    float best = fabsf(d[0]);
#pragma unroll
    for (int i = 1; i < DIM; ++i) {
        float ad = fabsf(d[i]);
        if (ad > best) { best = ad; worst = i; }
    }
    const bool odd = (isum & 1) != 0;
#pragma unroll
    for (int i = 0; i < DIM; ++i) {
        float step = (d[i] >= 0.0f) ? 1.0f : -1.0f;
        float g = f[i] + step;
        out[i] = (odd && (i == worst)) ? g : f[i];
    }
}

__device__ __noinline__ void slow_row(const float v[DIM], float r[DIM]) {
    float c0[DIM];
    closest_D8_exact(v, c0);
    float vs[DIM], c1[DIM];
#pragma unroll
    for (int i = 0; i < DIM; ++i) vs[i] = v[i] - 0.5f;
    closest_D8_exact(vs, c1);
#pragma unroll
    for (int i = 0; i < DIM; ++i) c1[i] += 0.5f;
    float d0 = 0.0f, d1 = 0.0f;
#pragma unroll
    for (int i = 0; i < DIM; ++i) {
        float e0 = v[i] - c0[i];
        float e1 = v[i] - c1[i];
        d0 = fmaf(e0, e0, d0);
        d1 = fmaf(e1, e1, d1);
    }
    const bool take0 = (d0 <= d1);
#pragma unroll
    for (int i = 0; i < DIM; ++i) r[i] = take0 ? c0[i] : c1[i];
}

// ---------------- fast kernel ----------------
__global__ void __launch_bounds__(256)
e8_closest_kernel(const float4* __restrict__ xin, float4* __restrict__ outv, int n_rows) {
    int row = blockIdx.x * blockDim.x + threadIdx.x;
    if (row >= n_rows) return;

    const float4 A = xin[2 * (size_t)row];
    const float4 B = xin[2 * (size_t)row + 1];
    float x[DIM] = {A.x, A.y, A.z, A.w, B.x, B.y, B.z, B.w};

    // Round-half-even via magic constant (exact for |x| < 2^22; low mantissa
    // bit of t encodes parity of round(x)). All three ops are exact.
    const float MAG = 12582912.0f;  // 1.5 * 2^23
    float t[DIM], f[DIM], d[DIM];
    u32 tb[DIM], db[DIM];
#pragma unroll
    for (int i = 0; i < DIM; ++i) {
        t[i] = x[i] + MAG;
        f[i] = t[i] - MAG;   // == rintf(x[i]) bitwise
        d[i] = x[i] - f[i];  // exact residual in [-0.5, 0.5]
        tb[i] = __float_as_uint(t[i]);
        db[i] = __float_as_uint(d[i]);
    }

    // argmax|d| (coset-0 flip coord) and argmin|d| (== argmax|d1|, coset-1 flip
    // coord). Strict compares give first-occurrence ties, matching jnp.argmax.
    float amax = fabsf(d[0]), amin = fabsf(d[0]);
    int imax = 0, imin = 0;
#pragma unroll
    for (int i = 1; i < DIM; ++i) {
        float ad = fabsf(d[i]);
        if (ad > amax) { amax = ad; imax = i; }
        if (ad < amin) { amin = ad; imin = i; }
    }

    // parity of sum(f) from magic-add mantissa bits; parity of coset-1 sum
    // additionally flips with each strictly-negative residual (round(x-0.5)
    // = f-1 exactly when d<0, f when d>0; d==0 / |d|==0.5 cases are exact or
    // routed to the slow path).
    u32 T  = tb[0] ^ tb[1] ^ tb[2] ^ tb[3] ^ tb[4] ^ tb[5] ^ tb[6] ^ tb[7];
    u32 SG = db[0] ^ db[1] ^ db[2] ^ db[3] ^ db[4] ^ db[5] ^ db[6] ^ db[7];
    const bool odd0 = (T & 1u) != 0u;
    const bool odd1 = ((T ^ (SG >> 31)) & 1u) != 0u;

    // Sum of |d| (abs is a free operand modifier on FADD)
    float Asum = ((fabsf(d[0]) + fabsf(d[1])) + (fabsf(d[2]) + fabsf(d[3]))) +
                 ((fabsf(d[4]) + fabsf(d[5])) + (fabsf(d[6]) + fabsf(d[7])));

    // dist1 - dist0 = 2 - sum|d| + odd1*2*min|d| - odd0*(1 - 2*max|d|)
    float s0 = odd0 ? __fmaf_rn(-2.0f, amax, 1.0f) : 0.0f;
    float s1 = odd1 ? (amin + amin) : 0.0f;
    float Dd = ((2.0f - Asum) + s1) - s0;

    // Exact path for (a) d==0 ties, (b) all-|d|==0.5 flip ambiguity,
    // (c) coset decision too close to call analytically. ~1e-5 of rows.
    if ((amin == 0.0f) || (amin == 0.5f) || (fabsf(Dd) < 1e-5f)) {
        float r[DIM];
        slow_row(x, r);
        outv[2 * (size_t)row]     = make_float4(r[0], r[1], r[2], r[3]);
        outv[2 * (size_t)row + 1] = make_float4(r[4], r[5], r[6], r[7]);
        return;
    }

    const bool take0 = (Dd >= 0.0f);  // d0 <= d1 -> coset 0, matching reference

    // flip coordinate of the selected coset (8 = no flip)
    int wsel = take0 ? (odd0 ? imax : 8) : (odd1 ? imin : 8);

    // Every answer coordinate is f + kappa * copysign(0.5, d):
    //   coset0: kappa = 0 normal, 2 flipped; coset1: 1 normal, -1 flipped.
    float kb = take0 ? 0.0f : 1.0f;
    float kf = take0 ? 2.0f : -1.0f;

    float r[DIM];
#pragma unroll
    for (int i = 0; i < DIM; ++i) {
        float cs  = __uint_as_float((db[i] & 0x80000000u) | 0x3F000000u); // copysign(.5, d)
        float kap = (i == wsel) ? kf : kb;
        r[i] = __fmaf_rn(cs, kap, f[i]);
    }

    outv[2 * (size_t)row]     = make_float4(r[0], r[1], r[2], r[3]);
    outv[2 * (size_t)row + 1] = make_float4(r[4], r[5], r[6], r[7]);
}

extern "C" void kernel_launch(void* const* d_in, const int* in_sizes, int n_in,
                              void* d_out, int out_size) {
    const float4* x = (const float4*)d_in[0];
    float4* out = (float4*)d_out;
    const int n_rows = in_sizes[0] / DIM;
    const int threads = 256;
    const int blocks = (n_rows + threads - 1) / threads;
    e8_closest_kernel<<<blocks, threads>>>(x, out, n_rows);
}

// round 4
// speedup vs baseline: 1.0846x; 1.0846x over previous
#include <cuda_runtime.h>

#define DIM 8
typedef unsigned int u32;
typedef unsigned long long u64;

// packed f32x2 helpers (sm_103a): two independent RN fp32 adds per instruction
__device__ __forceinline__ u64 pk2(float lo, float hi) {
    u64 r; asm("mov.b64 %0,{%1,%2};" : "=l"(r) : "f"(lo), "f"(hi)); return r;
}
__device__ __forceinline__ void upk2(u64 v, float& lo, float& hi) {
    asm("mov.b64 {%0,%1},%2;" : "=f"(lo), "=f"(hi) : "l"(v));
}
__device__ __forceinline__ u64 add2(u64 a, u64 b) {
    u64 r; asm("add.rn.f32x2 %0,%1,%2;" : "=l"(r) : "l"(a), "l"(b)); return r;
}

__global__ void __launch_bounds__(256)
e8_closest_kernel(const float4* __restrict__ xin, float4* __restrict__ outv, int n_rows) {
    int row = blockIdx.x * blockDim.x + threadIdx.x;
    if (row >= n_rows) return;

    const float4 A = xin[2 * (size_t)row];
    const float4 B = xin[2 * (size_t)row + 1];
    float x[DIM] = {A.x, A.y, A.z, A.w, B.x, B.y, B.z, B.w};

    // Round-half-even via magic constant (bitwise == rintf for |x| < 2^22).
    // Low mantissa bit of t gives parity of f. All ops exact. Packed f32x2.
    const u64 MAG2  = 0x4B4000004B400000ull;  // {12582912, 12582912}
    const u64 NMAG2 = 0xCB400000CB400000ull;

    float t[DIM], f[DIM], d[DIM];
#pragma unroll
    for (int p = 0; p < 4; ++p) {
        u64 xp = pk2(x[2 * p], x[2 * p + 1]);
        u64 tp = add2(xp, MAG2);     // 3*2^22 + f ; mantissa LSB = parity(f)
        u64 fp = add2(tp, NMAG2);    // f = round-half-even(x), exact
        upk2(tp, t[2 * p], t[2 * p + 1]);
        upk2(fp, f[2 * p], f[2 * p + 1]);
    }
#pragma unroll
    for (int i = 0; i < DIM; ++i) d[i] = x[i] - f[i];  // exact residual

    u32 tb[DIM], db[DIM];
#pragma unroll
    for (int i = 0; i < DIM; ++i) {
        tb[i] = __float_as_uint(t[i]);
        db[i] = __float_as_uint(d[i]);
    }

    // argmax|d| (coset-0 flip) and argmin|d| (== argmax|d1|, coset-1 flip).
    // Strict > / < on exact residuals = first-occurrence ties (jnp.argmax).
    float amax = fabsf(d[0]), amin = amax;
    int imax = 0, imin = 0;
#pragma unroll
    for (int i = 1; i < DIM; ++i) {
        float ad = fabsf(d[i]);
        imax = (ad > amax) ? i : imax;  amax = fmaxf(amax, ad);
        imin = (ad < amin) ? i : imin;  amin = fminf(amin, ad);
    }

    // parity(sum f) from magic-add LSBs; coset-1 parity flips per negative d
    u32 T  = (tb[0] ^ tb[1]) ^ (tb[2] ^ tb[3]) ^ ((tb[4] ^ tb[5]) ^ (tb[6] ^ tb[7]));
    u32 SG = (db[0] ^ db[1]) ^ (db[2] ^ db[3]) ^ ((db[4] ^ db[5]) ^ (db[6] ^ db[7]));
    const bool odd0 = (T & 1u) != 0u;
    const bool odd1 = ((T ^ (SG >> 31)) & 1u) != 0u;

    float Asum = ((fabsf(d[0]) + fabsf(d[1])) + (fabsf(d[2]) + fabsf(d[3]))) +
                 ((fabsf(d[4]) + fabsf(d[5])) + (fabsf(d[6]) + fabsf(d[7])));

    // dist1 - dist0 = 2 - sum|d| + odd1*2*min|d| - odd0*(1 - 2*max|d|)
    float s0 = odd0 ? __fmaf_rn(-2.0f, amax, 1.0f) : 0.0f;
    float s1 = odd1 ? (amin + amin) : 0.0f;
    float Dd = ((2.0f - Asum) + s1) - s0;

    float r[DIM];

    // Guards: (a) amin < 2e-6 — covers d==0 and the zone where reference's
    // inexact (x-0.5) can round across the half-integer tie; (b) all |d|==0.5;
    // (c) coset decision too close for the analytic compare. ~1e-4 of rows.
    if ((amin < 2e-6f) || (amin == 0.5f) || (fabsf(Dd) < 1e-5f)) {
        // Bit-exact reference recompute, fully inlined, constant indices only.
        // Coset 0 from already-exact f/d/imax/odd0:
        float c0[DIM];
#pragma unroll
        for (int i = 0; i < DIM; ++i) {
            float step = (d[i] >= 0.0f) ? 1.0f : -1.0f;
            c0[i] = f[i] + ((odd0 && i == imax) ? step : 0.0f);
        }
        // Coset 1 the reference way:
        float y[DIM], f1[DIM], d1[DIM];
        int isum1 = 0;
#pragma unroll
        for (int i = 0; i < DIM; ++i) {
            y[i]  = x[i] - 0.5f;
            f1[i] = rintf(y[i]);
            d1[i] = y[i] - f1[i];
            isum1 += __float2int_rn(f1[i]);
        }
        int w1 = 0;
        float b1 = fabsf(d1[0]);
#pragma unroll
        for (int i = 1; i < DIM; ++i) {
            float ad = fabsf(d1[i]);
            if (ad > b1) { b1 = ad; w1 = i; }
        }
        const bool o1 = (isum1 & 1) != 0;
        float c1[DIM];
#pragma unroll
        for (int i = 0; i < DIM; ++i) {
            float step = (d1[i] >= 0.0f) ? 1.0f : -1.0f;
            c1[i] = (f1[i] + ((o1 && i == w1) ? step : 0.0f)) + 0.5f;
        }
        float s0q = 0.0f, s1q = 0.0f;
#pragma unroll
        for (int i = 0; i < DIM; ++i) {
            float e0 = x[i] - c0[i];
            float e1 = x[i] - c1[i];
            s0q = __fmaf_rn(e0, e0, s0q);
            s1q = __fmaf_rn(e1, e1, s1q);
        }
        const bool tk0 = (s0q <= s1q);
#pragma unroll
        for (int i = 0; i < DIM; ++i) r[i] = tk0 ? c0[i] : c1[i];
    } else {
        const bool take0 = (Dd >= 0.0f);  // d0 <= d1 -> coset 0
        int wsel = take0 ? (odd0 ? imax : 8) : (odd1 ? imin : 8);
        // answer coord = f + kappa * copysign(0.5, d):
        //   coset0: 0 normal, 2 flipped; coset1: 1 normal, -1 flipped
        float kb = take0 ? 0.0f : 1.0f;
        float kf = take0 ? 2.0f : -1.0f;
#pragma unroll
        for (int i = 0; i < DIM; ++i) {
            float cs  = __uint_as_float((db[i] & 0x80000000u) | 0x3F000000u);
            float kap = (i == wsel) ? kf : kb;
            r[i] = __fmaf_rn(cs, kap, f[i]);
        }
    }

    outv[2 * (size_t)row]     = make_float4(r[0], r[1], r[2], r[3]);
    outv[2 * (size_t)row + 1] = make_float4(r[4], r[5], r[6], r[7]);
}

extern "C" void kernel_launch(void* const* d_in, const int* in_sizes, int n_in,
                              void* d_out, int out_size) {
    const float4* x = (const float4*)d_in[0];
    float4* out = (float4*)d_out;
    const int n_rows = in_sizes[0] / DIM;
    const int threads = 256;
    const int blocks = (n_rows + threads - 1) / threads;
    e8_closest_kernel<<<blocks, threads>>>(x, out, n_rows);
}

// round 5
// speedup vs baseline: 1.1353x; 1.0468x over previous
#include <cuda_runtime.h>

#define DIM 8
typedef unsigned int u32;
typedef unsigned long long u64;

// packed f32x2 helpers (sm_103a)
__device__ __forceinline__ u64 pk2(float lo, float hi) {
    u64 r; asm("mov.b64 %0,{%1,%2};" : "=l"(r) : "f"(lo), "f"(hi)); return r;
}
__device__ __forceinline__ void upk2(u64 v, float& lo, float& hi) {
    asm("mov.b64 {%0,%1},%2;" : "=f"(lo), "=f"(hi) : "l"(v));
}
__device__ __forceinline__ u64 add2(u64 a, u64 b) {
    u64 r; asm("add.rn.f32x2 %0,%1,%2;" : "=l"(r) : "l"(a), "l"(b)); return r;
}

// streaming (evict-first) 128-bit load/store
__device__ __forceinline__ float4 ldcs4(const float4* p) {
    float4 v;
    asm("ld.global.cs.v4.f32 {%0,%1,%2,%3},[%4];"
        : "=f"(v.x), "=f"(v.y), "=f"(v.z), "=f"(v.w) : "l"(p));
    return v;
}
__device__ __forceinline__ void stcs4(float4* p, float4 v) {
    asm("st.global.cs.v4.f32 [%0],{%1,%2,%3,%4};"
        :: "l"(p), "f"(v.x), "f"(v.y), "f"(v.z), "f"(v.w));
}

// One E8 row decode: hot analytic path + inline bit-exact fallback.
// Fully unrolled, constant indices only — everything stays in registers.
__device__ __forceinline__ void e8_row(const float x[DIM], float r[DIM]) {
    const u64 MAG2  = 0x4B4000004B400000ull;  // {12582912, 12582912}
    const u64 NMAG2 = 0xCB400000CB400000ull;

    float t[DIM], f[DIM], d[DIM];
#pragma unroll
    for (int p = 0; p < 4; ++p) {
        u64 xp = pk2(x[2 * p], x[2 * p + 1]);
        u64 tp = add2(xp, MAG2);     // mantissa LSB = parity(round(x))
        u64 fp = add2(tp, NMAG2);    // f = round-half-even(x), exact
        upk2(tp, t[2 * p], t[2 * p + 1]);
        upk2(fp, f[2 * p], f[2 * p + 1]);
    }
#pragma unroll
    for (int i = 0; i < DIM; ++i) d[i] = x[i] - f[i];  // exact

    u32 tb[DIM], db[DIM];
#pragma unroll
    for (int i = 0; i < DIM; ++i) {
        tb[i] = __float_as_uint(t[i]);
        db[i] = __float_as_uint(d[i]);
    }

    // argmax|d| / argmin|d|, first-occurrence ties
    float amax = fabsf(d[0]), amin = amax;
    int imax = 0, imin = 0;
#pragma unroll
    for (int i = 1; i < DIM; ++i) {
        float ad = fabsf(d[i]);
        imax = (ad > amax) ? i : imax;  amax = fmaxf(amax, ad);
        imin = (ad < amin) ? i : imin;  amin = fminf(amin, ad);
    }

    u32 T  = (tb[0] ^ tb[1]) ^ (tb[2] ^ tb[3]) ^ ((tb[4] ^ tb[5]) ^ (tb[6] ^ tb[7]));
    u32 SG = (db[0] ^ db[1]) ^ (db[2] ^ db[3]) ^ ((db[4] ^ db[5]) ^ (db[6] ^ db[7]));
    const bool odd0 = (T & 1u) != 0u;
    const bool odd1 = ((T ^ (SG >> 31)) & 1u) != 0u;

    float Asum = ((fabsf(d[0]) + fabsf(d[1])) + (fabsf(d[2]) + fabsf(d[3]))) +
                 ((fabsf(d[4]) + fabsf(d[5])) + (fabsf(d[6]) + fabsf(d[7])));

    // dist1 - dist0 = 2 - sum|d| + odd1*2*min|d| - odd0*(1 - 2*max|d|)
    float s0 = odd0 ? __fmaf_rn(-2.0f, amax, 1.0f) : 0.0f;
    float s1 = odd1 ? (amin + amin) : 0.0f;
    float Dd = ((2.0f - Asum) + s1) - s0;

    if ((amin < 2e-6f) || (amin == 0.5f) || (fabsf(Dd) < 1e-5f)) {
        // Bit-exact reference recompute (rare: ~1e-4 of rows).
        float c0[DIM];
#pragma unroll
        for (int i = 0; i < DIM; ++i) {
            float step = (d[i] >= 0.0f) ? 1.0f : -1.0f;
            c0[i] = f[i] + ((odd0 && i == imax) ? step : 0.0f);
        }
        float y[DIM], f1[DIM], d1[DIM];
        int isum1 = 0;
#pragma unroll
        for (int i = 0; i < DIM; ++i) {
            y[i]  = x[i] - 0.5f;
            f1[i] = rintf(y[i]);
            d1[i] = y[i] - f1[i];
            isum1 += __float2int_rn(f1[i]);
        }
        int w1 = 0;
        float b1 = fabsf(d1[0]);
#pragma unroll
        for (int i = 1; i < DIM; ++i) {
            float ad = fabsf(d1[i]);
            if (ad > b1) { b1 = ad; w1 = i; }
        }
        const bool o1 = (isum1 & 1) != 0;
        float c1[DIM];
#pragma unroll
        for (int i = 0; i < DIM; ++i) {
            float step = (d1[i] >= 0.0f) ? 1.0f : -1.0f;
            c1[i] = (f1[i] + ((o1 && i == w1) ? step : 0.0f)) + 0.5f;
        }
        float s0q = 0.0f, s1q = 0.0f;
#pragma unroll
        for (int i = 0; i < DIM; ++i) {
            float e0 = x[i] - c0[i];
            float e1 = x[i] - c1[i];
            s0q = __fmaf_rn(e0, e0, s0q);
            s1q = __fmaf_rn(e1, e1, s1q);
        }
        const bool tk0 = (s0q <= s1q);
#pragma unroll
        for (int i = 0; i < DIM; ++i) r[i] = tk0 ? c0[i] : c1[i];
    } else {
        const bool take0 = (Dd >= 0.0f);
        int wsel = take0 ? (odd0 ? imax : 8) : (odd1 ? imin : 8);
        float kb = take0 ? 0.0f : 1.0f;
        float kf = take0 ? 2.0f : -1.0f;
#pragma unroll
        for (int i = 0; i < DIM; ++i) {
            float cs  = __uint_as_float((db[i] & 0x80000000u) | 0x3F000000u);
            float kap = (i == wsel) ? kf : kb;
            r[i] = __fmaf_rn(cs, kap, f[i]);
        }
    }
}

// 2 rows per thread, 4 front-batched LDG.128 for MLP, streaming cache hints.
__global__ void __launch_bounds__(256)
e8_closest_kernel(const float4* __restrict__ xin, float4* __restrict__ outv, int n_rows) {
    int tid = blockIdx.x * blockDim.x + threadIdx.x;
    size_t r0 = 2 * (size_t)tid;       // first row of this thread's pair
    size_t r1 = r0 + 1;
    if ((int)r0 >= n_rows) return;
    const bool has2 = ((int)r1 < n_rows);

    // Front-batched loads (MLP_p1 = 4)
    float4 A0 = ldcs4(xin + 2 * r0);
    float4 B0 = ldcs4(xin + 2 * r0 + 1);
    float4 A1 = has2 ? ldcs4(xin + 2 * r1)     : make_float4(0, 0, 0, 0);
    float4 B1 = has2 ? ldcs4(xin + 2 * r1 + 1) : make_float4(0, 0, 0, 0);

    {
        float x[DIM] = {A0.x, A0.y, A0.z, A0.w, B0.x, B0.y, B0.z, B0.w};
        float r[DIM];
        e8_row(x, r);
        stcs4(outv + 2 * r0,     make_float4(r[0], r[1], r[2], r[3]));
        stcs4(outv + 2 * r0 + 1, make_float4(r[4], r[5], r[6], r[7]));
    }
    if (has2) {
        float x[DIM] = {A1.x, A1.y, A1.z, A1.w, B1.x, B1.y, B1.z, B1.w};
        float r[DIM];
        e8_row(x, r);
        stcs4(outv + 2 * r1,     make_float4(r[0], r[1], r[2], r[3]));
        stcs4(outv + 2 * r1 + 1, make_float4(r[4], r[5], r[6], r[7]));
    }
}

extern "C" void kernel_launch(void* const* d_in, const int* in_sizes, int n_in,
                              void* d_out, int out_size) {
    const float4* x = (const float4*)d_in[0];
    float4* out = (float4*)d_out;
    const int n_rows = in_sizes[0] / DIM;
    const int threads = 256;
    const int rows_per_block = threads * 2;
    const int blocks = (n_rows + rows_per_block - 1) / rows_per_block;
    e8_closest_kernel<<<blocks, threads>>>(x, out, n_rows);
}